// round 14
// baseline (speedup 1.0000x reference)
#include <cuda_runtime.h>
#include <cuda_fp16.h>

typedef unsigned long long u64;
typedef unsigned int u32;

// ---------------- scalar helpers ----------------
static __device__ __forceinline__ float tanh_hw(float x) {
    float y; asm("tanh.approx.f32 %0, %1;" : "=f"(y) : "f"(x)); return y;
}
static __device__ __forceinline__ u32 f22h2(float lo, float hi) {
    __half2 h = __floats2half2_rn(lo, hi);
    return *reinterpret_cast<u32*>(&h);
}
static __device__ __forceinline__ u32 tp(float a, float b) {
    return f22h2(tanh_hw(a), tanh_hw(b));
}

static constexpr u32 H2_ONE_ONE = 0x3C003C00u;   // half2{1.0, 1.0}
static constexpr u32 H2_HI_ONE  = 0x3C000000u;   // high half = 1.0

// ---------------- mma.m16n8k16 f16*f16 -> f32 ----------------
static __device__ __forceinline__ void mma_16816(float c[4], const u32 a[4], u32 b0, u32 b1) {
    asm volatile(
        "mma.sync.aligned.m16n8k16.row.col.f32.f16.f16.f32 "
        "{%0,%1,%2,%3}, {%4,%5,%6,%7}, {%8,%9}, {%0,%1,%2,%3};"
        : "+f"(c[0]), "+f"(c[1]), "+f"(c[2]), "+f"(c[3])
        : "r"(a[0]), "r"(a[1]), "r"(a[2]), "r"(a[3]), "r"(b0), "r"(b1));
}

// ---------------- register-resident B fragments ----------------
template <int NT, int KT, int KP>
struct BFrag { u32 v[NT][KT][2]; };

template <int NT, int KT, int KP>
static __device__ __forceinline__ void load_bfrag(BFrag<NT, KT, KP>& f,
                                                  const __half* wt, int g, int qi) {
#pragma unroll
    for (int nt = 0; nt < NT; nt++)
#pragma unroll
        for (int kt = 0; kt < KT; kt++) {
            const __half* base = wt + (nt * 8 + g) * KP + kt * 16 + 2 * qi;
            f.v[nt][kt][0] = *(const u32*)base;
            f.v[nt][kt][1] = *(const u32*)(base + 8);
        }
}

template <int NT, int KT, int KP>
static __device__ __forceinline__ void mma_frag(float (*c)[4], const u32 (*a)[4],
                                                const BFrag<NT, KT, KP>& f) {
#pragma unroll
    for (int nt = 0; nt < NT; nt++)
#pragma unroll
        for (int kt = 0; kt < KT; kt++)
            mma_16816(c[nt], a[kt], f.v[nt][kt][0], f.v[nt][kt][1]);
}

template <int NT>
static __device__ __forceinline__ void zero4(float (*c)[4]) {
#pragma unroll
    for (int nt = 0; nt < NT; nt++) { c[nt][0] = 0.f; c[nt][1] = 0.f; c[nt][2] = 0.f; c[nt][3] = 0.f; }
}
template <int NT>
static __device__ __forceinline__ void binit(float (*c)[4], const float2* bb) {
#pragma unroll
    for (int nt = 0; nt < NT; nt++) {
        c[nt][0] = bb[nt].x; c[nt][1] = bb[nt].y;
        c[nt][2] = bb[nt].x; c[nt][3] = bb[nt].y;
    }
}

// C (4 N-tiles, 32 cols) -> A (2 K-tiles); bias slots k=30(hi),31(lo) -> 1.0 (qi==3)
static __device__ __forceinline__ void act_trans_w(u32 (*a)[4], const float (*c)[4], int qi) {
    a[0][0] = tp(c[0][0], c[0][1]); a[0][1] = tp(c[0][2], c[0][3]);
    a[0][2] = tp(c[1][0], c[1][1]); a[0][3] = tp(c[1][2], c[1][3]);
    a[1][0] = tp(c[2][0], c[2][1]); a[1][1] = tp(c[2][2], c[2][3]);
    u32 t2 = tp(c[3][0], c[3][1]);
    u32 t3 = tp(c[3][2], c[3][3]);
    a[1][2] = (qi == 3) ? H2_ONE_ONE : t2;   // k=30 hi, k=31 lo
    a[1][3] = (qi == 3) ? H2_ONE_ONE : t3;
}

// C (2 N-tiles, 16 cols) -> A (1 K-tile); k=15 (high half, qi==3) -> 1.0 (zero row: harmless)
static __device__ __forceinline__ void act_trans_p(u32 a[4], const float (*c)[4], int qi) {
    a[0] = tp(c[0][0], c[0][1]); a[1] = tp(c[0][2], c[0][3]);
    u32 t2 = tp(c[1][0], c[1][1]);
    u32 t3 = tp(c[1][2], c[1][3]);
    a[2] = (qi == 3) ? ((t2 & 0xFFFFu) | H2_HI_ONE) : t2;
    a[3] = (qi == 3) ? ((t3 & 0xFFFFu) | H2_HI_ONE) : t3;
}

// ---------------- smem layout (halves), [n][KP] ----------------
static constexpr int SW1 = 0;     // [32][16]  bias hi/lo at k=2,3
static constexpr int SW2 = 512;   // [32][32]  bias hi/lo at k=30,31
static constexpr int SW3 = 1536;  // [32][32]  bias hi/lo at k=30,31
static constexpr int SW4 = 2560;  // [8][32]   bias hi/lo at k=30,31
static constexpr int SP1 = 2816;  // [16][16]  bias hi/lo at k=2,3
static constexpr int SP2 = 3072;  // [16][16]  no fold (fp32 reg bias)
static constexpr int SP3 = 3328;  // [16][16]  no fold
static constexpr int SP4 = 3584;  // [8][16]   no fold
static constexpr int WT_TOTAL = 3712;
static constexpr int HSTRIDE = 13;

// ---------------- half-angle + epilogue ----------------
static __device__ __forceinline__ void halfang(float c, float sn, float& sh, float& ch) {
    ch = sqrtf(fmaxf(0.0f, 0.5f * (1.0f + c)));
    float sh_a = copysignf(sqrtf(fmaxf(0.0f, 0.5f * (1.0f - c))), sn);
    float sh_b = __fdividef(0.5f * sn, ch);
    sh = (ch > 0.1f) ? sh_b : sh_a;
}
static __device__ __forceinline__ float epilogue(
    float x0, float x1, float r, float cb, float sb,
    const float* wv, const float* pv, float lm)
{
    float s2  = fmaf(x0, x0, x1 * x1);
    float ri0 = rsqrtf(s2);
    float r0  = s2 * ri0;
    float c   = x0 * ri0, sn = x1 * ri0;
    float sh, ch; halfang(c, sn, sh, ch);
    float sq  = sqrtf(r0);
    float v0  = sq * sh;
    float v1  = r0 * sn;
    float v2  = (r0 * sq) * fmaf(sn, ch, c * sh);
    float shb, chb; halfang(cb, sb, shb, chb);
    float u0 = shb, u1 = sb, u2 = fmaf(sb, chb, cb * shb);
    float t  = fminf(fmaxf(fmaf(2.5f, r, -1.25f), 0.0f), 1.0f);
    float t3 = t * t * t;
    float yita = fmaf(fmaf(fmaf(-6.0f, t, 15.0f), t, -10.0f), t3, 1.0f);
    float rp = wv[0] + yita * wv[4]
             + fmaf(wv[5], yita, wv[1]) * v0
             + fmaf(wv[6], yita, wv[2]) * v1
             + fmaf(wv[7], yita, wv[3]) * v2;
    float s  = fmaf(pv[1], u0, fmaf(pv[2], u1, fmaf(pv[3], u2, pv[0])));
    float sp = s * yita * __powf(r, lm);
    return rp + sp;
}

// ---------------- kernel: 64 points/warp; weights in regs; hi/lo bias fold ----------------
__global__ void __launch_bounds__(128)
mlp2d_kernel(const float* __restrict__ x,   const float* __restrict__ imv,
             const float* __restrict__ lmbd,
             const float* __restrict__ Ww1, const float* __restrict__ bw1,
             const float* __restrict__ Ww2, const float* __restrict__ bw2,
             const float* __restrict__ Ww3, const float* __restrict__ bw3,
             const float* __restrict__ Ww4, const float* __restrict__ bw4,
             const float* __restrict__ Wp1, const float* __restrict__ bp1,
             const float* __restrict__ Wp2, const float* __restrict__ bp2,
             const float* __restrict__ Wp3, const float* __restrict__ bp3,
             const float* __restrict__ Wp4, const float* __restrict__ bp4,
             float* __restrict__ out, long long N)
{
    __shared__ alignas(16) __half WT[WT_TOTAL];
    __shared__ alignas(16) float  XF[4][256];
    __shared__ alignas(16) float  HB[4][64 * HSTRIDE];
    __shared__ float scons[3];

    const int tid = threadIdx.x;

    // ---- stage weights transposed [n][KP]; bias hi/lo folded where room ----
    {
        struct WSeg { const float* w; const float* b; int off, KP, NP, KI, NO, fold; };
        const WSeg ws[8] = {
            {Ww1, bw1, SW1, 16, 32, 2, 30, 1},  {Ww2, bw2, SW2, 32, 32, 30, 30, 1},
            {Ww3, bw3, SW3, 32, 32, 30, 30, 1}, {Ww4, bw4, SW4, 32, 8, 30, 8, 1},
            {Wp1, bp1, SP1, 16, 16, 2, 15, 1},  {Wp2, bp2, SP2, 16, 16, 15, 15, 0},
            {Wp3, bp3, SP3, 16, 16, 15, 15, 0}, {Wp4, bp4, SP4, 16, 8, 15, 4, 0},
        };
        for (int a = 0; a < 8; a++) {
            const WSeg s = ws[a];
            int n_el = s.NP * s.KP;
            for (int t = tid; t < n_el; t += 128) {
                int n = t / s.KP, k = t - n * s.KP;
                __half hv = __float2half(0.0f);
                if (n < s.NO) {
                    if (k < s.KI) {
                        hv = __float2half(s.w[k * s.NO + n]);
                    } else if (s.fold && (k == s.KI || k == s.KI + 1)) {
                        float bv = s.b[n];
                        __half hi = __float2half(bv);
                        hv = (k == s.KI) ? hi : __float2half(bv - __half2float(hi));
                    }
                }
                WT[s.off + t] = hv;
            }
        }
        if (tid == 0) { scons[0] = imv[0]; scons[1] = imv[1]; scons[2] = lmbd[0]; }
    }
    __syncthreads();

    const int lane = tid & 31;
    const int warp = tid >> 5;
    const int g = lane >> 2;
    const int qi = lane & 3;

    long long warpBase = ((long long)blockIdx.x * 4 + warp) * 64;
    if (warpBase >= N) return;

    // ---- load my 2 points + geometry; stage inputs ----
    long long i0 = warpBase + 2 * lane;
    long long iload = (i0 + 1 < N) ? i0 : (N - 2);
    float4 p = *(const float4*)(x + 2 * (size_t)iload);
    float xa0 = p.x, xa1 = p.y, xb0 = p.z, xb1 = p.w;

    const float im0 = scons[0], im1 = scons[1], lm = scons[2];
    float dA0 = xa0 - im0, dA1 = xa1 - im1;
    float rsA = fmaf(dA0, dA0, dA1 * dA1);
    float riA = rsqrtf(rsA);
    float rA = rsA * riA, cbA = dA0 * riA, sbA = dA1 * riA;
    float dB0 = xb0 - im0, dB1 = xb1 - im1;
    float rsB = fmaf(dB0, dB0, dB1 * dB1);
    float riB = rsqrtf(rsB);
    float rB = rsB * riB, cbB = dB0 * riB, sbB = dB1 * riB;

    float* Xb = &XF[warp][0];
    float* Fb = &XF[warp][128];
    float* Hb = &HB[warp][0];
    {
        int r0 = 2 * lane, r1 = r0 + 1;
        Xb[2 * r0] = xa0; Xb[2 * r0 + 1] = xa1;
        Xb[2 * r1] = xb0; Xb[2 * r1 + 1] = xb1;
        Fb[2 * r0] = cbA; Fb[2 * r0 + 1] = sbA;
        Fb[2 * r1] = cbB; Fb[2 * r1 + 1] = sbB;
    }
    __syncwarp();

    // ---- hoist all B fragments into registers (loaded once) ----
    BFrag<4, 1, 16> fw1; load_bfrag(fw1, WT + SW1, g, qi);
    BFrag<4, 2, 32> fw2; load_bfrag(fw2, WT + SW2, g, qi);
    BFrag<4, 2, 32> fw3; load_bfrag(fw3, WT + SW3, g, qi);
    BFrag<1, 2, 32> fw4; load_bfrag(fw4, WT + SW4, g, qi);
    BFrag<2, 1, 16> fp1; load_bfrag(fp1, WT + SP1, g, qi);
    BFrag<2, 1, 16> fp2; load_bfrag(fp2, WT + SP2, g, qi);
    BFrag<2, 1, 16> fp3; load_bfrag(fp3, WT + SP3, g, qi);
    BFrag<1, 1, 16> fp4; load_bfrag(fp4, WT + SP4, g, qi);

    // ---- fp32 bias registers for p2/p3/p4 (no fold room at KI=15) ----
    float2 bbp2[2], bbp3[2], bbp4[1];
    {
        int c0 = 2 * qi;
#pragma unroll
        for (int nt = 0; nt < 2; nt++) {
            int c = nt * 8 + c0;
            bbp2[nt].x = (c < 15) ? bp2[c] : 0.f;
            bbp2[nt].y = (c + 1 < 15) ? bp2[c + 1] : 0.f;
            bbp3[nt].x = (c < 15) ? bp3[c] : 0.f;
            bbp3[nt].y = (c + 1 < 15) ? bp3[c + 1] : 0.f;
        }
        bbp4[0].x = (c0 < 4) ? bp4[c0] : 0.f;
        bbp4[0].y = (c0 + 1 < 4) ? bp4[c0 + 1] : 0.f;
    }

    // ---- per-M-tile network ----
#pragma unroll 1
    for (int mt = 0; mt < 4; mt++) {
        int row0 = mt * 16 + g, row1 = row0 + 8;

        // ===== w-MLP =====
        u32 aL1[1][4];
        aL1[0][0] = (qi == 0) ? f22h2(Xb[2 * row0], Xb[2 * row0 + 1])
                              : ((qi == 1) ? H2_ONE_ONE : 0u);   // k=2 hi, k=3 lo
        aL1[0][1] = (qi == 0) ? f22h2(Xb[2 * row1], Xb[2 * row1 + 1])
                              : ((qi == 1) ? H2_ONE_ONE : 0u);
        aL1[0][2] = 0u; aL1[0][3] = 0u;

        float cw[4][4];
        zero4<4>(cw);
        mma_frag(cw, aL1, fw1);

        u32 aw[2][4];
        act_trans_w(aw, cw, qi);
        zero4<4>(cw);
        mma_frag(cw, aw, fw2);

        act_trans_w(aw, cw, qi);
        zero4<4>(cw);
        mma_frag(cw, aw, fw3);

        act_trans_w(aw, cw, qi);
        float c4[1][4];
        zero4<1>(c4);
        mma_frag(c4, aw, fw4);

        Hb[row0 * HSTRIDE + 2 * qi]     = c4[0][0];
        Hb[row0 * HSTRIDE + 2 * qi + 1] = c4[0][1];
        Hb[row1 * HSTRIDE + 2 * qi]     = c4[0][2];
        Hb[row1 * HSTRIDE + 2 * qi + 1] = c4[0][3];

        // ===== phi-MLP =====
        u32 aP1[1][4];
        aP1[0][0] = (qi == 0) ? f22h2(Fb[2 * row0], Fb[2 * row0 + 1])
                              : ((qi == 1) ? H2_ONE_ONE : 0u);
        aP1[0][1] = (qi == 0) ? f22h2(Fb[2 * row1], Fb[2 * row1 + 1])
                              : ((qi == 1) ? H2_ONE_ONE : 0u);
        aP1[0][2] = 0u; aP1[0][3] = 0u;

        float cp[2][4];
        zero4<2>(cp);
        mma_frag(cp, aP1, fp1);

        u32 ap[1][4];
        act_trans_p(ap[0], cp, qi);
        binit<2>(cp, bbp2);
        mma_frag(cp, ap, fp2);

        act_trans_p(ap[0], cp, qi);
        binit<2>(cp, bbp3);
        mma_frag(cp, ap, fp3);

        act_trans_p(ap[0], cp, qi);
        float cp4[1][4];
        binit<1>(cp4, bbp4);
        mma_frag(cp4, ap, fp4);

        if (qi < 2) {
            Hb[row0 * HSTRIDE + 8 + 2 * qi]     = cp4[0][0];
            Hb[row0 * HSTRIDE + 8 + 2 * qi + 1] = cp4[0][1];
            Hb[row1 * HSTRIDE + 8 + 2 * qi]     = cp4[0][2];
            Hb[row1 * HSTRIDE + 8 + 2 * qi + 1] = cp4[0][3];
        }
    }
    __syncwarp();

    // ---- epilogue on my own 2 points ----
    {
        int r0 = 2 * lane, r1 = r0 + 1;
        float wv[8], pv[4];
#pragma unroll
        for (int j = 0; j < 8; j++) wv[j] = Hb[r0 * HSTRIDE + j];
#pragma unroll
        for (int j = 0; j < 4; j++) pv[j] = Hb[r0 * HSTRIDE + 8 + j];
        float eA = epilogue(xa0, xa1, rA, cbA, sbA, wv, pv, lm);

#pragma unroll
        for (int j = 0; j < 8; j++) wv[j] = Hb[r1 * HSTRIDE + j];
#pragma unroll
        for (int j = 0; j < 4; j++) pv[j] = Hb[r1 * HSTRIDE + 8 + j];
        float eB = epilogue(xb0, xb1, rB, cbB, sbB, wv, pv, lm);

        if (i0 + 1 < N) {
            *(float2*)(out + i0) = make_float2(eA, eB);
        } else if (i0 < N) {
            out[i0] = eA;
        }
    }
}

extern "C" void kernel_launch(void* const* d_in, const int* in_sizes, int n_in,
                              void* d_out, int out_size)
{
    const float* x    = (const float*)d_in[0];
    const float* imv  = (const float*)d_in[1];
    const float* lmbd = (const float*)d_in[2];
    const float* Ww1  = (const float*)d_in[3];
    const float* bw1  = (const float*)d_in[4];
    const float* Ww2  = (const float*)d_in[5];
    const float* bw2  = (const float*)d_in[6];
    const float* Ww3  = (const float*)d_in[7];
    const float* bw3  = (const float*)d_in[8];
    const float* Ww4  = (const float*)d_in[9];
    const float* bw4  = (const float*)d_in[10];
    const float* Wp1  = (const float*)d_in[11];
    const float* bp1  = (const float*)d_in[12];
    const float* Wp2  = (const float*)d_in[13];
    const float* bp2  = (const float*)d_in[14];
    const float* Wp3  = (const float*)d_in[15];
    const float* bp3  = (const float*)d_in[16];
    const float* Wp4  = (const float*)d_in[17];
    const float* bp4  = (const float*)d_in[18];

    long long N = out_size;
    long long blocks = (N + 255) / 256;

    mlp2d_kernel<<<(int)blocks, 128>>>(x, imv, lmbd,
                                       Ww1, bw1, Ww2, bw2, Ww3, bw3, Ww4, bw4,
                                       Wp1, bp1, Wp2, bp2, Wp3, bp3, Wp4, bp4,
                                       (float*)d_out, N);
}

// round 15
// speedup vs baseline: 1.6249x; 1.6249x over previous
#include <cuda_runtime.h>
#include <cuda_fp16.h>

typedef unsigned long long u64;
typedef unsigned int u32;

// ---------------- scalar helpers ----------------
static __device__ __forceinline__ float tanh_hw(float x) {
    float y; asm("tanh.approx.f32 %0, %1;" : "=f"(y) : "f"(x)); return y;
}
static __device__ __forceinline__ u32 f22h2(float lo, float hi) {
    __half2 h = __floats2half2_rn(lo, hi);
    return *reinterpret_cast<u32*>(&h);
}
static __device__ __forceinline__ u32 tp(float a, float b) {
    return f22h2(tanh_hw(a), tanh_hw(b));
}

static constexpr u32 H2_ONE_ONE = 0x3C003C00u;   // half2{1.0, 1.0}
static constexpr u32 H2_HI_ONE  = 0x3C000000u;   // high half = 1.0

// ---------------- mma.m16n8k16 f16*f16 -> f32 ----------------
static __device__ __forceinline__ void mma_16816(float c[4], const u32 a[4], u32 b0, u32 b1) {
    asm volatile(
        "mma.sync.aligned.m16n8k16.row.col.f32.f16.f16.f32 "
        "{%0,%1,%2,%3}, {%4,%5,%6,%7}, {%8,%9}, {%0,%1,%2,%3};"
        : "+f"(c[0]), "+f"(c[1]), "+f"(c[2]), "+f"(c[3])
        : "r"(a[0]), "r"(a[1]), "r"(a[2]), "r"(a[3]), "r"(b0), "r"(b1));
}

// fragment-packed weights: PK[seg][frag][lane] = uint2{b0,b1}; one LDS.64 per MMA
template <int NT, int KT>
static __device__ __forceinline__ void mma_pk(float (*c)[4], const u32 (*a)[4],
                                              const uint2* __restrict__ segp) {
#pragma unroll
    for (int nt = 0; nt < NT; nt++)
#pragma unroll
        for (int kt = 0; kt < KT; kt++) {
            uint2 w = segp[(nt * KT + kt) * 32];
            mma_16816(c[nt], a[kt], w.x, w.y);
        }
}

template <int NT>
static __device__ __forceinline__ void zero4(float (*c)[4]) {
#pragma unroll
    for (int nt = 0; nt < NT; nt++) { c[nt][0] = 0.f; c[nt][1] = 0.f; c[nt][2] = 0.f; c[nt][3] = 0.f; }
}
template <int NT>
static __device__ __forceinline__ void binit(float (*c)[4], const float2* bb) {
#pragma unroll
    for (int nt = 0; nt < NT; nt++) {
        c[nt][0] = bb[nt].x; c[nt][1] = bb[nt].y;
        c[nt][2] = bb[nt].x; c[nt][3] = bb[nt].y;
    }
}

// C (4 N-tiles, 32 cols) -> A (2 K-tiles); bias slots k=30(hi),31(lo) -> 1.0 (qi==3)
static __device__ __forceinline__ void act_trans_w(u32 (*a)[4], const float (*c)[4], int qi) {
    a[0][0] = tp(c[0][0], c[0][1]); a[0][1] = tp(c[0][2], c[0][3]);
    a[0][2] = tp(c[1][0], c[1][1]); a[0][3] = tp(c[1][2], c[1][3]);
    a[1][0] = tp(c[2][0], c[2][1]); a[1][1] = tp(c[2][2], c[2][3]);
    u32 t2 = tp(c[3][0], c[3][1]);
    u32 t3 = tp(c[3][2], c[3][3]);
    a[1][2] = (qi == 3) ? H2_ONE_ONE : t2;   // k=30 hi, k=31 lo
    a[1][3] = (qi == 3) ? H2_ONE_ONE : t3;
}

// C (2 N-tiles, 16 cols) -> A (1 K-tile); k=15 (high half, qi==3) -> 1.0 (zero weight row)
static __device__ __forceinline__ void act_trans_p(u32 a[4], const float (*c)[4], int qi) {
    a[0] = tp(c[0][0], c[0][1]); a[1] = tp(c[0][2], c[0][3]);
    u32 t2 = tp(c[1][0], c[1][1]);
    u32 t3 = tp(c[1][2], c[1][3]);
    a[2] = (qi == 3) ? ((t2 & 0xFFFFu) | H2_HI_ONE) : t2;
    a[3] = (qi == 3) ? ((t3 & 0xFFFFu) | H2_HI_ONE) : t3;
}

// ---------------- packed-fragment smem offsets (uint2 units) ----------------
static constexpr int PW1 = 0;     // NT=4 KT=1 -> 128
static constexpr int PW2 = 128;   // NT=4 KT=2 -> 256
static constexpr int PW3 = 384;   // 256
static constexpr int PW4 = 640;   // NT=1 KT=2 -> 64
static constexpr int PP1 = 704;   // NT=2 KT=1 -> 64
static constexpr int PP2 = 768;   // 64
static constexpr int PP3 = 832;   // 64
static constexpr int PP4 = 896;   // NT=1 KT=1 -> 32
static constexpr int PK_TOTAL = 928;   // uint2 = 7424 B
static constexpr int HSTRIDE = 13;

// ---------------- half-angle + epilogue ----------------
static __device__ __forceinline__ void halfang(float c, float sn, float& sh, float& ch) {
    ch = sqrtf(fmaxf(0.0f, 0.5f * (1.0f + c)));
    float sh_a = copysignf(sqrtf(fmaxf(0.0f, 0.5f * (1.0f - c))), sn);
    float sh_b = __fdividef(0.5f * sn, ch);
    sh = (ch > 0.1f) ? sh_b : sh_a;
}
static __device__ __forceinline__ float epilogue(
    float x0, float x1, float r, float cb, float sb,
    const float* wv, const float* pv, float lm)
{
    float s2  = fmaf(x0, x0, x1 * x1);
    float ri0 = rsqrtf(s2);
    float r0  = s2 * ri0;
    float c   = x0 * ri0, sn = x1 * ri0;
    float sh, ch; halfang(c, sn, sh, ch);
    float sq  = sqrtf(r0);
    float v0  = sq * sh;
    float v1  = r0 * sn;
    float v2  = (r0 * sq) * fmaf(sn, ch, c * sh);
    float shb, chb; halfang(cb, sb, shb, chb);
    float u0 = shb, u1 = sb, u2 = fmaf(sb, chb, cb * shb);
    float t  = fminf(fmaxf(fmaf(2.5f, r, -1.25f), 0.0f), 1.0f);
    float t3 = t * t * t;
    float yita = fmaf(fmaf(fmaf(-6.0f, t, 15.0f), t, -10.0f), t3, 1.0f);
    float rp = wv[0] + yita * wv[4]
             + fmaf(wv[5], yita, wv[1]) * v0
             + fmaf(wv[6], yita, wv[2]) * v1
             + fmaf(wv[7], yita, wv[3]) * v2;
    float s  = fmaf(pv[1], u0, fmaf(pv[2], u1, fmaf(pv[3], u2, pv[0])));
    float sp = s * yita * __powf(r, lm);
    return rp + sp;
}

// ---------------- kernel: 64 points/warp; packed LDS.64 fragments ----------------
__global__ void __launch_bounds__(128)
mlp2d_kernel(const float* __restrict__ x,   const float* __restrict__ imv,
             const float* __restrict__ lmbd,
             const float* __restrict__ Ww1, const float* __restrict__ bw1,
             const float* __restrict__ Ww2, const float* __restrict__ bw2,
             const float* __restrict__ Ww3, const float* __restrict__ bw3,
             const float* __restrict__ Ww4, const float* __restrict__ bw4,
             const float* __restrict__ Wp1, const float* __restrict__ bp1,
             const float* __restrict__ Wp2, const float* __restrict__ bp2,
             const float* __restrict__ Wp3, const float* __restrict__ bp3,
             const float* __restrict__ Wp4, const float* __restrict__ bp4,
             float* __restrict__ out, long long N)
{
    __shared__ alignas(16) uint2 PK[PK_TOTAL];
    __shared__ alignas(16) float XF[4][256];
    __shared__ alignas(16) float HB[4][64 * HSTRIDE];
    __shared__ float scons[3];

    const int tid = threadIdx.x;

    // ---- stage fragment-packed weights (bias hi/lo folded where room) ----
    {
        struct WSeg { const float* w; const float* b; int off, NT, KT, KI, NO, fold; };
        const WSeg ws[8] = {
            {Ww1, bw1, PW1, 4, 1, 2, 30, 1},  {Ww2, bw2, PW2, 4, 2, 30, 30, 1},
            {Ww3, bw3, PW3, 4, 2, 30, 30, 1}, {Ww4, bw4, PW4, 1, 2, 30, 8, 1},
            {Wp1, bp1, PP1, 2, 1, 2, 15, 1},  {Wp2, bp2, PP2, 2, 1, 15, 15, 0},
            {Wp3, bp3, PP3, 2, 1, 15, 15, 0}, {Wp4, bp4, PP4, 1, 1, 15, 4, 0},
        };
        for (int a = 0; a < 8; a++) {
            const WSeg s = ws[a];
            int n_u32 = s.NT * s.KT * 64;            // 2 u32 per (frag,lane)
            for (int t = tid; t < n_u32; t += 128) {
                int pairIdx = t >> 1, half = t & 1;
                int lanep = pairIdx & 31, blk = pairIdx >> 5;
                int nt = blk / s.KT, kt = blk - nt * s.KT;
                int gg = lanep >> 2, qq = lanep & 3;
                int n = nt * 8 + gg;
                int k0 = kt * 16 + 2 * qq + (half ? 8 : 0);
                float v0f = 0.f, v1f = 0.f;
                if (n < s.NO) {
                    for (int e = 0; e < 2; e++) {
                        int k = k0 + e;
                        float v = 0.f;
                        if (k < s.KI) v = s.w[k * s.NO + n];
                        else if (s.fold && k == s.KI) {
                            v = __half2float(__float2half(s.b[n]));     // hi
                        } else if (s.fold && k == s.KI + 1) {
                            float bv = s.b[n];
                            v = bv - __half2float(__float2half(bv));    // lo
                        }
                        if (e == 0) v0f = v; else v1f = v;
                    }
                }
                ((u32*)PK)[s.off * 2 + t] = f22h2(v0f, v1f);
            }
        }
        if (tid == 0) { scons[0] = imv[0]; scons[1] = imv[1]; scons[2] = lmbd[0]; }
    }
    __syncthreads();

    const int lane = tid & 31;
    const int warp = tid >> 5;
    const int g = lane >> 2;
    const int qi = lane & 3;

    long long warpBase = ((long long)blockIdx.x * 4 + warp) * 64;
    if (warpBase >= N) return;

    // ---- load my 2 points + geometry; stage inputs ----
    long long i0 = warpBase + 2 * lane;
    long long iload = (i0 + 1 < N) ? i0 : (N - 2);
    float4 p = *(const float4*)(x + 2 * (size_t)iload);
    float xa0 = p.x, xa1 = p.y, xb0 = p.z, xb1 = p.w;

    const float im0 = scons[0], im1 = scons[1], lm = scons[2];
    float dA0 = xa0 - im0, dA1 = xa1 - im1;
    float rsA = fmaf(dA0, dA0, dA1 * dA1);
    float riA = rsqrtf(rsA);
    float rA = rsA * riA, cbA = dA0 * riA, sbA = dA1 * riA;
    float dB0 = xb0 - im0, dB1 = xb1 - im1;
    float rsB = fmaf(dB0, dB0, dB1 * dB1);
    float riB = rsqrtf(rsB);
    float rB = rsB * riB, cbB = dB0 * riB, sbB = dB1 * riB;

    float* Xb = &XF[warp][0];
    float* Fb = &XF[warp][128];
    float* Hb = &HB[warp][0];
    {
        int r0 = 2 * lane, r1 = r0 + 1;
        Xb[2 * r0] = xa0; Xb[2 * r0 + 1] = xa1;
        Xb[2 * r1] = xb0; Xb[2 * r1 + 1] = xb1;
        Fb[2 * r0] = cbA; Fb[2 * r0 + 1] = sbA;
        Fb[2 * r1] = cbB; Fb[2 * r1 + 1] = sbB;
    }
    __syncwarp();

    // ---- per-lane segment pointers (base + lane; frag index is immediate) ----
    const uint2* pw1 = PK + PW1 + lane;
    const uint2* pw2 = PK + PW2 + lane;
    const uint2* pw3 = PK + PW3 + lane;
    const uint2* pw4 = PK + PW4 + lane;
    const uint2* pp1 = PK + PP1 + lane;
    const uint2* pp2 = PK + PP2 + lane;
    const uint2* pp3 = PK + PP3 + lane;
    const uint2* pp4 = PK + PP4 + lane;

    // ---- fp32 bias registers for p2/p3/p4 (no fold room at KI=15) ----
    float2 bbp2[2], bbp3[2], bbp4[1];
    {
        int c0 = 2 * qi;
#pragma unroll
        for (int nt = 0; nt < 2; nt++) {
            int c = nt * 8 + c0;
            bbp2[nt].x = (c < 15) ? bp2[c] : 0.f;
            bbp2[nt].y = (c + 1 < 15) ? bp2[c + 1] : 0.f;
            bbp3[nt].x = (c < 15) ? bp3[c] : 0.f;
            bbp3[nt].y = (c + 1 < 15) ? bp3[c + 1] : 0.f;
        }
        bbp4[0].x = (c0 < 4) ? bp4[c0] : 0.f;
        bbp4[0].y = (c0 + 1 < 4) ? bp4[c0 + 1] : 0.f;
    }

    // ---- per-M-tile network ----
#pragma unroll 1
    for (int mt = 0; mt < 4; mt++) {
        int row0 = mt * 16 + g, row1 = row0 + 8;

        // ===== w-MLP =====
        u32 aL1[1][4];
        aL1[0][0] = (qi == 0) ? f22h2(Xb[2 * row0], Xb[2 * row0 + 1])
                              : ((qi == 1) ? H2_ONE_ONE : 0u);   // k=2 hi, k=3 lo
        aL1[0][1] = (qi == 0) ? f22h2(Xb[2 * row1], Xb[2 * row1 + 1])
                              : ((qi == 1) ? H2_ONE_ONE : 0u);
        aL1[0][2] = 0u; aL1[0][3] = 0u;

        float cw[4][4];
        zero4<4>(cw);
        mma_pk<4, 1>(cw, aL1, pw1);

        u32 aw[2][4];
        act_trans_w(aw, cw, qi);
        zero4<4>(cw);
        mma_pk<4, 2>(cw, aw, pw2);

        act_trans_w(aw, cw, qi);
        zero4<4>(cw);
        mma_pk<4, 2>(cw, aw, pw3);

        act_trans_w(aw, cw, qi);
        float c4[1][4];
        zero4<1>(c4);
        mma_pk<1, 2>(c4, aw, pw4);

        Hb[row0 * HSTRIDE + 2 * qi]     = c4[0][0];
        Hb[row0 * HSTRIDE + 2 * qi + 1] = c4[0][1];
        Hb[row1 * HSTRIDE + 2 * qi]     = c4[0][2];
        Hb[row1 * HSTRIDE + 2 * qi + 1] = c4[0][3];

        // ===== phi-MLP =====
        u32 aP1[1][4];
        aP1[0][0] = (qi == 0) ? f22h2(Fb[2 * row0], Fb[2 * row0 + 1])
                              : ((qi == 1) ? H2_ONE_ONE : 0u);
        aP1[0][1] = (qi == 0) ? f22h2(Fb[2 * row1], Fb[2 * row1 + 1])
                              : ((qi == 1) ? H2_ONE_ONE : 0u);
        aP1[0][2] = 0u; aP1[0][3] = 0u;

        float cp[2][4];
        zero4<2>(cp);
        mma_pk<2, 1>(cp, aP1, pp1);

        u32 ap[1][4];
        act_trans_p(ap[0], cp, qi);
        binit<2>(cp, bbp2);
        mma_pk<2, 1>(cp, ap, pp2);

        act_trans_p(ap[0], cp, qi);
        binit<2>(cp, bbp3);
        mma_pk<2, 1>(cp, ap, pp3);

        act_trans_p(ap[0], cp, qi);
        float cp4[1][4];
        binit<1>(cp4, bbp4);
        mma_pk<1, 1>(cp4, ap, pp4);

        if (qi < 2) {
            Hb[row0 * HSTRIDE + 8 + 2 * qi]     = cp4[0][0];
            Hb[row0 * HSTRIDE + 8 + 2 * qi + 1] = cp4[0][1];
            Hb[row1 * HSTRIDE + 8 + 2 * qi]     = cp4[0][2];
            Hb[row1 * HSTRIDE + 8 + 2 * qi + 1] = cp4[0][3];
        }
    }
    __syncwarp();

    // ---- epilogue on my own 2 points ----
    {
        int r0 = 2 * lane, r1 = r0 + 1;
        float wv[8], pv[4];
#pragma unroll
        for (int j = 0; j < 8; j++) wv[j] = Hb[r0 * HSTRIDE + j];
#pragma unroll
        for (int j = 0; j < 4; j++) pv[j] = Hb[r0 * HSTRIDE + 8 + j];
        float eA = epilogue(xa0, xa1, rA, cbA, sbA, wv, pv, lm);

#pragma unroll
        for (int j = 0; j < 8; j++) wv[j] = Hb[r1 * HSTRIDE + j];
#pragma unroll
        for (int j = 0; j < 4; j++) pv[j] = Hb[r1 * HSTRIDE + 8 + j];
        float eB = epilogue(xb0, xb1, rB, cbB, sbB, wv, pv, lm);

        if (i0 + 1 < N) {
            *(float2*)(out + i0) = make_float2(eA, eB);
        } else if (i0 < N) {
            out[i0] = eA;
        }
    }
}

extern "C" void kernel_launch(void* const* d_in, const int* in_sizes, int n_in,
                              void* d_out, int out_size)
{
    const float* x    = (const float*)d_in[0];
    const float* imv  = (const float*)d_in[1];
    const float* lmbd = (const float*)d_in[2];
    const float* Ww1  = (const float*)d_in[3];
    const float* bw1  = (const float*)d_in[4];
    const float* Ww2  = (const float*)d_in[5];
    const float* bw2  = (const float*)d_in[6];
    const float* Ww3  = (const float*)d_in[7];
    const float* bw3  = (const float*)d_in[8];
    const float* Ww4  = (const float*)d_in[9];
    const float* bw4  = (const float*)d_in[10];
    const float* Wp1  = (const float*)d_in[11];
    const float* bp1  = (const float*)d_in[12];
    const float* Wp2  = (const float*)d_in[13];
    const float* bp2  = (const float*)d_in[14];
    const float* Wp3  = (const float*)d_in[15];
    const float* bp3  = (const float*)d_in[16];
    const float* Wp4  = (const float*)d_in[17];
    const float* bp4  = (const float*)d_in[18];

    long long N = out_size;
    long long blocks = (N + 255) / 256;

    mlp2d_kernel<<<(int)blocks, 128>>>(x, imv, lmbd,
                                       Ww1, bw1, Ww2, bw2, Ww3, bw3, Ww4, bw4,
                                       Wp1, bp1, Wp2, bp2, Wp3, bp3, Wp4, bp4,
                                       (float*)d_out, N);
}

// round 16
// speedup vs baseline: 1.6725x; 1.0293x over previous
#include <cuda_runtime.h>
#include <cuda_fp16.h>

typedef unsigned long long u64;
typedef unsigned int u32;

// ---------------- scalar helpers ----------------
static __device__ __forceinline__ float tanh_hw(float x) {
    float y; asm("tanh.approx.f32 %0, %1;" : "=f"(y) : "f"(x)); return y;
}
static __device__ __forceinline__ u32 f22h2(float lo, float hi) {
    __half2 h = __floats2half2_rn(lo, hi);
    return *reinterpret_cast<u32*>(&h);
}
static __device__ __forceinline__ u32 tp(float a, float b) {
    return f22h2(tanh_hw(a), tanh_hw(b));
}

static constexpr u32 H2_ONE_ONE = 0x3C003C00u;   // half2{1.0, 1.0}
static constexpr u32 H2_HI_ONE  = 0x3C000000u;   // high half = 1.0

// ---------------- mma.m16n8k16 f16*f16 -> f32 ----------------
static __device__ __forceinline__ void mma_16816(float c[4], const u32 a[4], u32 b0, u32 b1) {
    asm volatile(
        "mma.sync.aligned.m16n8k16.row.col.f32.f16.f16.f32 "
        "{%0,%1,%2,%3}, {%4,%5,%6,%7}, {%8,%9}, {%0,%1,%2,%3};"
        : "+f"(c[0]), "+f"(c[1]), "+f"(c[2]), "+f"(c[3])
        : "r"(a[0]), "r"(a[1]), "r"(a[2]), "r"(a[3]), "r"(b0), "r"(b1));
}

// fragment-packed weights: PK[seg][frag][lane] = uint2{b0,b1}; one LDS.64 per MMA
template <int NT, int KT>
static __device__ __forceinline__ void mma_pk(float (*c)[4], const u32 (*a)[4],
                                              const uint2* __restrict__ segp) {
#pragma unroll
    for (int nt = 0; nt < NT; nt++)
#pragma unroll
        for (int kt = 0; kt < KT; kt++) {
            uint2 w = segp[(nt * KT + kt) * 32];
            mma_16816(c[nt], a[kt], w.x, w.y);
        }
}

template <int NT>
static __device__ __forceinline__ void zero4(float (*c)[4]) {
#pragma unroll
    for (int nt = 0; nt < NT; nt++) { c[nt][0] = 0.f; c[nt][1] = 0.f; c[nt][2] = 0.f; c[nt][3] = 0.f; }
}
template <int NT>
static __device__ __forceinline__ void binit(float (*c)[4], const float2* bb) {
#pragma unroll
    for (int nt = 0; nt < NT; nt++) {
        c[nt][0] = bb[nt].x; c[nt][1] = bb[nt].y;
        c[nt][2] = bb[nt].x; c[nt][3] = bb[nt].y;
    }
}

// C (4 N-tiles, 32 cols) -> A (2 K-tiles); bias slots k=30(hi),31(lo) -> 1.0 (qi==3)
static __device__ __forceinline__ void act_trans_w(u32 (*a)[4], const float (*c)[4], int qi) {
    a[0][0] = tp(c[0][0], c[0][1]); a[0][1] = tp(c[0][2], c[0][3]);
    a[0][2] = tp(c[1][0], c[1][1]); a[0][3] = tp(c[1][2], c[1][3]);
    a[1][0] = tp(c[2][0], c[2][1]); a[1][1] = tp(c[2][2], c[2][3]);
    u32 t2 = tp(c[3][0], c[3][1]);
    u32 t3 = tp(c[3][2], c[3][3]);
    a[1][2] = (qi == 3) ? H2_ONE_ONE : t2;   // k=30 hi, k=31 lo
    a[1][3] = (qi == 3) ? H2_ONE_ONE : t3;
}

// C (2 N-tiles, 16 cols) -> A (1 K-tile); k=15 (high half, qi==3) -> 1.0 (zero weight row)
static __device__ __forceinline__ void act_trans_p(u32 a[4], const float (*c)[4], int qi) {
    a[0] = tp(c[0][0], c[0][1]); a[1] = tp(c[0][2], c[0][3]);
    u32 t2 = tp(c[1][0], c[1][1]);
    u32 t3 = tp(c[1][2], c[1][3]);
    a[2] = (qi == 3) ? ((t2 & 0xFFFFu) | H2_HI_ONE) : t2;
    a[3] = (qi == 3) ? ((t3 & 0xFFFFu) | H2_HI_ONE) : t3;
}

// ---------------- packed-fragment offsets (uint2 units) ----------------
static constexpr int PW1 = 0;     // NT=4 KT=1 -> 128
static constexpr int PW2 = 128;   // NT=4 KT=2 -> 256
static constexpr int PW3 = 384;   // 256
static constexpr int PW4 = 640;   // NT=1 KT=2 -> 64
static constexpr int PP1 = 704;   // NT=2 KT=1 -> 64
static constexpr int PP2 = 768;   // 64
static constexpr int PP3 = 832;   // 64
static constexpr int PP4 = 896;   // NT=1 KT=1 -> 32
static constexpr int PK_TOTAL = 928;   // uint2 = 7424 B
static constexpr int HSTRIDE = 13;

// global staging buffer (written by stage_kernel, read by main kernel)
__device__ alignas(16) uint2 g_PK[PK_TOTAL];

// ---------------- half-angle + epilogue ----------------
static __device__ __forceinline__ void halfang(float c, float sn, float& sh, float& ch) {
    ch = sqrtf(fmaxf(0.0f, 0.5f * (1.0f + c)));
    float sh_a = copysignf(sqrtf(fmaxf(0.0f, 0.5f * (1.0f - c))), sn);
    float sh_b = __fdividef(0.5f * sn, ch);
    sh = (ch > 0.1f) ? sh_b : sh_a;
}
static __device__ __forceinline__ float epilogue(
    float x0, float x1, float r, float cb, float sb,
    const float* wv, const float* pv, float lm)
{
    float s2  = fmaf(x0, x0, x1 * x1);
    float ri0 = rsqrtf(s2);
    float r0  = s2 * ri0;
    float c   = x0 * ri0, sn = x1 * ri0;
    float sh, ch; halfang(c, sn, sh, ch);
    float sq  = sqrtf(r0);
    float v0  = sq * sh;
    float v1  = r0 * sn;
    float v2  = (r0 * sq) * fmaf(sn, ch, c * sh);
    float shb, chb; halfang(cb, sb, shb, chb);
    float u0 = shb, u1 = sb, u2 = fmaf(sb, chb, cb * shb);
    float t  = fminf(fmaxf(fmaf(2.5f, r, -1.25f), 0.0f), 1.0f);
    float t3 = t * t * t;
    float yita = fmaf(fmaf(fmaf(-6.0f, t, 15.0f), t, -10.0f), t3, 1.0f);
    float rp = wv[0] + yita * wv[4]
             + fmaf(wv[5], yita, wv[1]) * v0
             + fmaf(wv[6], yita, wv[2]) * v1
             + fmaf(wv[7], yita, wv[3]) * v2;
    float s  = fmaf(pv[1], u0, fmaf(pv[2], u1, fmaf(pv[3], u2, pv[0])));
    float sp = s * yita * __powf(r, lm);
    return rp + sp;
}

// ---------------- stage kernel: build packed-fragment image ONCE ----------------
__global__ void stage_kernel(const float* __restrict__ Ww1, const float* __restrict__ bw1,
                             const float* __restrict__ Ww2, const float* __restrict__ bw2,
                             const float* __restrict__ Ww3, const float* __restrict__ bw3,
                             const float* __restrict__ Ww4, const float* __restrict__ bw4,
                             const float* __restrict__ Wp1, const float* __restrict__ bp1,
                             const float* __restrict__ Wp2, const float* __restrict__ bp2,
                             const float* __restrict__ Wp3, const float* __restrict__ bp3,
                             const float* __restrict__ Wp4, const float* __restrict__ bp4)
{
    const int tid = threadIdx.x;
    struct WSeg { const float* w; const float* b; int off, NT, KT, KI, NO, fold; };
    const WSeg ws[8] = {
        {Ww1, bw1, PW1, 4, 1, 2, 30, 1},  {Ww2, bw2, PW2, 4, 2, 30, 30, 1},
        {Ww3, bw3, PW3, 4, 2, 30, 30, 1}, {Ww4, bw4, PW4, 1, 2, 30, 8, 1},
        {Wp1, bp1, PP1, 2, 1, 2, 15, 1},  {Wp2, bp2, PP2, 2, 1, 15, 15, 0},
        {Wp3, bp3, PP3, 2, 1, 15, 15, 0}, {Wp4, bp4, PP4, 1, 1, 15, 4, 0},
    };
    for (int a = 0; a < 8; a++) {
        const WSeg s = ws[a];
        int n_u32 = s.NT * s.KT * 64;
        for (int t = tid; t < n_u32; t += 128) {
            int pairIdx = t >> 1, half = t & 1;
            int lanep = pairIdx & 31, blk = pairIdx >> 5;
            int nt = blk / s.KT, kt = blk - nt * s.KT;
            int gg = lanep >> 2, qq = lanep & 3;
            int n = nt * 8 + gg;
            int k0 = kt * 16 + 2 * qq + (half ? 8 : 0);
            float v0f = 0.f, v1f = 0.f;
            if (n < s.NO) {
                for (int e = 0; e < 2; e++) {
                    int k = k0 + e;
                    float v = 0.f;
                    if (k < s.KI) v = s.w[k * s.NO + n];
                    else if (s.fold && k == s.KI) {
                        v = __half2float(__float2half(s.b[n]));     // hi
                    } else if (s.fold && k == s.KI + 1) {
                        float bv = s.b[n];
                        v = bv - __half2float(__float2half(bv));    // lo
                    }
                    if (e == 0) v0f = v; else v1f = v;
                }
            }
            ((u32*)g_PK)[s.off * 2 + t] = f22h2(v0f, v1f);
        }
    }
}

// ---------------- main kernel: 64 points/warp; packed LDS.64 fragments ----------------
__global__ void __launch_bounds__(128)
mlp2d_kernel(const float* __restrict__ x,   const float* __restrict__ imv,
             const float* __restrict__ lmbd,
             const float* __restrict__ bp2, const float* __restrict__ bp3,
             const float* __restrict__ bp4,
             float* __restrict__ out, long long N)
{
    __shared__ alignas(16) uint2 PK[PK_TOTAL];
    __shared__ alignas(16) float XF[4][256];
    __shared__ alignas(16) float HB[4][64 * HSTRIDE];
    __shared__ float scons[3];

    const int tid = threadIdx.x;

    // ---- copy packed weights global -> smem (vectorized) ----
    {
        const uint4* src = (const uint4*)g_PK;
        uint4* dst = (uint4*)PK;
#pragma unroll
        for (int t = tid; t < PK_TOTAL / 2; t += 128)   // 464 uint4
            dst[t] = src[t];
        if (tid == 0) { scons[0] = imv[0]; scons[1] = imv[1]; scons[2] = lmbd[0]; }
    }
    __syncthreads();

    const int lane = tid & 31;
    const int warp = tid >> 5;
    const int g = lane >> 2;
    const int qi = lane & 3;

    long long warpBase = ((long long)blockIdx.x * 4 + warp) * 64;
    if (warpBase >= N) return;

    // ---- load my 2 points + geometry; stage inputs ----
    long long i0 = warpBase + 2 * lane;
    long long iload = (i0 + 1 < N) ? i0 : (N - 2);
    float4 p = *(const float4*)(x + 2 * (size_t)iload);
    float xa0 = p.x, xa1 = p.y, xb0 = p.z, xb1 = p.w;

    const float im0 = scons[0], im1 = scons[1], lm = scons[2];
    float dA0 = xa0 - im0, dA1 = xa1 - im1;
    float rsA = fmaf(dA0, dA0, dA1 * dA1);
    float riA = rsqrtf(rsA);
    float rA = rsA * riA, cbA = dA0 * riA, sbA = dA1 * riA;
    float dB0 = xb0 - im0, dB1 = xb1 - im1;
    float rsB = fmaf(dB0, dB0, dB1 * dB1);
    float riB = rsqrtf(rsB);
    float rB = rsB * riB, cbB = dB0 * riB, sbB = dB1 * riB;

    float* Xb = &XF[warp][0];
    float* Fb = &XF[warp][128];
    float* Hb = &HB[warp][0];
    {
        int r0 = 2 * lane, r1 = r0 + 1;
        Xb[2 * r0] = xa0; Xb[2 * r0 + 1] = xa1;
        Xb[2 * r1] = xb0; Xb[2 * r1 + 1] = xb1;
        Fb[2 * r0] = cbA; Fb[2 * r0 + 1] = sbA;
        Fb[2 * r1] = cbB; Fb[2 * r1 + 1] = sbB;
    }
    __syncwarp();

    // ---- per-lane segment pointers ----
    const uint2* pw1 = PK + PW1 + lane;
    const uint2* pw2 = PK + PW2 + lane;
    const uint2* pw3 = PK + PW3 + lane;
    const uint2* pw4 = PK + PW4 + lane;
    const uint2* pp1 = PK + PP1 + lane;
    const uint2* pp2 = PK + PP2 + lane;
    const uint2* pp3 = PK + PP3 + lane;
    const uint2* pp4 = PK + PP4 + lane;

    // ---- fp32 bias registers for p2/p3/p4 ----
    float2 bbp2[2], bbp3[2], bbp4[1];
    {
        int c0 = 2 * qi;
#pragma unroll
        for (int nt = 0; nt < 2; nt++) {
            int c = nt * 8 + c0;
            bbp2[nt].x = (c < 15) ? bp2[c] : 0.f;
            bbp2[nt].y = (c + 1 < 15) ? bp2[c + 1] : 0.f;
            bbp3[nt].x = (c < 15) ? bp3[c] : 0.f;
            bbp3[nt].y = (c + 1 < 15) ? bp3[c + 1] : 0.f;
        }
        bbp4[0].x = (c0 < 4) ? bp4[c0] : 0.f;
        bbp4[0].y = (c0 + 1 < 4) ? bp4[c0 + 1] : 0.f;
    }

    // ---- per-M-tile network ----
#pragma unroll 1
    for (int mt = 0; mt < 4; mt++) {
        int row0 = mt * 16 + g, row1 = row0 + 8;

        // ===== w-MLP =====
        u32 aL1[1][4];
        aL1[0][0] = (qi == 0) ? f22h2(Xb[2 * row0], Xb[2 * row0 + 1])
                              : ((qi == 1) ? H2_ONE_ONE : 0u);   // k=2 hi, k=3 lo
        aL1[0][1] = (qi == 0) ? f22h2(Xb[2 * row1], Xb[2 * row1 + 1])
                              : ((qi == 1) ? H2_ONE_ONE : 0u);
        aL1[0][2] = 0u; aL1[0][3] = 0u;

        float cw[4][4];
        zero4<4>(cw);
        mma_pk<4, 1>(cw, aL1, pw1);

        u32 aw[2][4];
        act_trans_w(aw, cw, qi);
        zero4<4>(cw);
        mma_pk<4, 2>(cw, aw, pw2);

        act_trans_w(aw, cw, qi);
        zero4<4>(cw);
        mma_pk<4, 2>(cw, aw, pw3);

        act_trans_w(aw, cw, qi);
        float c4[1][4];
        zero4<1>(c4);
        mma_pk<1, 2>(c4, aw, pw4);

        Hb[row0 * HSTRIDE + 2 * qi]     = c4[0][0];
        Hb[row0 * HSTRIDE + 2 * qi + 1] = c4[0][1];
        Hb[row1 * HSTRIDE + 2 * qi]     = c4[0][2];
        Hb[row1 * HSTRIDE + 2 * qi + 1] = c4[0][3];

        // ===== phi-MLP =====
        u32 aP1[1][4];
        aP1[0][0] = (qi == 0) ? f22h2(Fb[2 * row0], Fb[2 * row0 + 1])
                              : ((qi == 1) ? H2_ONE_ONE : 0u);
        aP1[0][1] = (qi == 0) ? f22h2(Fb[2 * row1], Fb[2 * row1 + 1])
                              : ((qi == 1) ? H2_ONE_ONE : 0u);
        aP1[0][2] = 0u; aP1[0][3] = 0u;

        float cp[2][4];
        zero4<2>(cp);
        mma_pk<2, 1>(cp, aP1, pp1);

        u32 ap[1][4];
        act_trans_p(ap[0], cp, qi);
        binit<2>(cp, bbp2);
        mma_pk<2, 1>(cp, ap, pp2);

        act_trans_p(ap[0], cp, qi);
        binit<2>(cp, bbp3);
        mma_pk<2, 1>(cp, ap, pp3);

        act_trans_p(ap[0], cp, qi);
        float cp4[1][4];
        binit<1>(cp4, bbp4);
        mma_pk<1, 1>(cp4, ap, pp4);

        if (qi < 2) {
            Hb[row0 * HSTRIDE + 8 + 2 * qi]     = cp4[0][0];
            Hb[row0 * HSTRIDE + 8 + 2 * qi + 1] = cp4[0][1];
            Hb[row1 * HSTRIDE + 8 + 2 * qi]     = cp4[0][2];
            Hb[row1 * HSTRIDE + 8 + 2 * qi + 1] = cp4[0][3];
        }
    }
    __syncwarp();

    // ---- epilogue on my own 2 points ----
    {
        int r0 = 2 * lane, r1 = r0 + 1;
        float wv[8], pv[4];
#pragma unroll
        for (int j = 0; j < 8; j++) wv[j] = Hb[r0 * HSTRIDE + j];
#pragma unroll
        for (int j = 0; j < 4; j++) pv[j] = Hb[r0 * HSTRIDE + 8 + j];
        float eA = epilogue(xa0, xa1, rA, cbA, sbA, wv, pv, lm);

#pragma unroll
        for (int j = 0; j < 8; j++) wv[j] = Hb[r1 * HSTRIDE + j];
#pragma unroll
        for (int j = 0; j < 4; j++) pv[j] = Hb[r1 * HSTRIDE + 8 + j];
        float eB = epilogue(xb0, xb1, rB, cbB, sbB, wv, pv, lm);

        if (i0 + 1 < N) {
            *(float2*)(out + i0) = make_float2(eA, eB);
        } else if (i0 < N) {
            out[i0] = eA;
        }
    }
}

extern "C" void kernel_launch(void* const* d_in, const int* in_sizes, int n_in,
                              void* d_out, int out_size)
{
    const float* x    = (const float*)d_in[0];
    const float* imv  = (const float*)d_in[1];
    const float* lmbd = (const float*)d_in[2];
    const float* Ww1  = (const float*)d_in[3];
    const float* bw1  = (const float*)d_in[4];
    const float* Ww2  = (const float*)d_in[5];
    const float* bw2  = (const float*)d_in[6];
    const float* Ww3  = (const float*)d_in[7];
    const float* bw3  = (const float*)d_in[8];
    const float* Ww4  = (const float*)d_in[9];
    const float* bw4  = (const float*)d_in[10];
    const float* Wp1  = (const float*)d_in[11];
    const float* bp1  = (const float*)d_in[12];
    const float* Wp2  = (const float*)d_in[13];
    const float* bp2  = (const float*)d_in[14];
    const float* Wp3  = (const float*)d_in[15];
    const float* bp3  = (const float*)d_in[16];
    const float* Wp4  = (const float*)d_in[17];
    const float* bp4  = (const float*)d_in[18];

    long long N = out_size;
    long long blocks = (N + 255) / 256;

    stage_kernel<<<1, 128>>>(Ww1, bw1, Ww2, bw2, Ww3, bw3, Ww4, bw4,
                             Wp1, bp1, Wp2, bp2, Wp3, bp3, Wp4, bp4);
    mlp2d_kernel<<<(int)blocks, 128>>>(x, imv, lmbd, bp2, bp3, bp4,
                                       (float*)d_out, N);
}

// round 17
// speedup vs baseline: 1.7967x; 1.0742x over previous
#include <cuda_runtime.h>
#include <cuda_fp16.h>

typedef unsigned long long u64;
typedef unsigned int u32;

// ---------------- scalar helpers ----------------
static __device__ __forceinline__ u32 f22h2(float lo, float hi) {
    __half2 h = __floats2half2_rn(lo, hi);
    return *reinterpret_cast<u32*>(&h);
}
// pack fp32 pair -> fp16x2, then ONE MUFU tanh on both halves
static __device__ __forceinline__ u32 tph2(float a, float b) {
    u32 h = f22h2(a, b);
    u32 y; asm("tanh.approx.f16x2 %0, %1;" : "=r"(y) : "r"(h));
    return y;
}

static constexpr u32 H2_ONE_ONE = 0x3C003C00u;   // half2{1.0, 1.0}
static constexpr u32 H2_HI_ONE  = 0x3C000000u;   // high half = 1.0

// ---------------- mma.m16n8k16 f16*f16 -> f32 ----------------
static __device__ __forceinline__ void mma_16816(float c[4], const u32 a[4], u32 b0, u32 b1) {
    asm volatile(
        "mma.sync.aligned.m16n8k16.row.col.f32.f16.f16.f32 "
        "{%0,%1,%2,%3}, {%4,%5,%6,%7}, {%8,%9}, {%0,%1,%2,%3};"
        : "+f"(c[0]), "+f"(c[1]), "+f"(c[2]), "+f"(c[3])
        : "r"(a[0]), "r"(a[1]), "r"(a[2]), "r"(a[3]), "r"(b0), "r"(b1));
}

// fragment-packed weights: PK[seg][frag][lane] = uint2{b0,b1}; one LDS.64 per MMA
template <int NT, int KT>
static __device__ __forceinline__ void mma_pk(float (*c)[4], const u32 (*a)[4],
                                              const uint2* __restrict__ segp) {
#pragma unroll
    for (int nt = 0; nt < NT; nt++)
#pragma unroll
        for (int kt = 0; kt < KT; kt++) {
            uint2 w = segp[(nt * KT + kt) * 32];
            mma_16816(c[nt], a[kt], w.x, w.y);
        }
}

template <int NT>
static __device__ __forceinline__ void zero4(float (*c)[4]) {
#pragma unroll
    for (int nt = 0; nt < NT; nt++) { c[nt][0] = 0.f; c[nt][1] = 0.f; c[nt][2] = 0.f; c[nt][3] = 0.f; }
}
template <int NT>
static __device__ __forceinline__ void binit(float (*c)[4], const float2* bb) {
#pragma unroll
    for (int nt = 0; nt < NT; nt++) {
        c[nt][0] = bb[nt].x; c[nt][1] = bb[nt].y;
        c[nt][2] = bb[nt].x; c[nt][3] = bb[nt].y;
    }
}

// C (4 N-tiles, 32 cols) -> A (2 K-tiles); bias slots k=30(hi),31(lo) -> 1.0 (qi==3)
static __device__ __forceinline__ void act_trans_w(u32 (*a)[4], const float (*c)[4], int qi) {
    a[0][0] = tph2(c[0][0], c[0][1]); a[0][1] = tph2(c[0][2], c[0][3]);
    a[0][2] = tph2(c[1][0], c[1][1]); a[0][3] = tph2(c[1][2], c[1][3]);
    a[1][0] = tph2(c[2][0], c[2][1]); a[1][1] = tph2(c[2][2], c[2][3]);
    u32 t2 = tph2(c[3][0], c[3][1]);
    u32 t3 = tph2(c[3][2], c[3][3]);
    a[1][2] = (qi == 3) ? H2_ONE_ONE : t2;   // k=30 hi, k=31 lo
    a[1][3] = (qi == 3) ? H2_ONE_ONE : t3;
}

// C (2 N-tiles, 16 cols) -> A (1 K-tile); k=15 (high half, qi==3) -> 1.0 (zero weight row)
static __device__ __forceinline__ void act_trans_p(u32 a[4], const float (*c)[4], int qi) {
    a[0] = tph2(c[0][0], c[0][1]); a[1] = tph2(c[0][2], c[0][3]);
    u32 t2 = tph2(c[1][0], c[1][1]);
    u32 t3 = tph2(c[1][2], c[1][3]);
    a[2] = (qi == 3) ? ((t2 & 0xFFFFu) | H2_HI_ONE) : t2;
    a[3] = (qi == 3) ? ((t3 & 0xFFFFu) | H2_HI_ONE) : t3;
}

// ---------------- packed-fragment offsets (uint2 units) ----------------
static constexpr int PW1 = 0;     // NT=4 KT=1 -> 128
static constexpr int PW2 = 128;   // NT=4 KT=2 -> 256
static constexpr int PW3 = 384;   // 256
static constexpr int PW4 = 640;   // NT=1 KT=2 -> 64
static constexpr int PP1 = 704;   // NT=2 KT=1 -> 64
static constexpr int PP2 = 768;   // 64
static constexpr int PP3 = 832;   // 64
static constexpr int PP4 = 896;   // NT=1 KT=1 -> 32
static constexpr int PK_TOTAL = 928;   // uint2 = 7424 B
static constexpr int HSTRIDE = 13;

// global staging buffer (written by stage_kernel, read by main kernel)
__device__ alignas(16) uint2 g_PK[PK_TOTAL];

// ---------------- half-angle + epilogue ----------------
static __device__ __forceinline__ void halfang(float c, float sn, float& sh, float& ch) {
    ch = sqrtf(fmaxf(0.0f, 0.5f * (1.0f + c)));
    float sh_a = copysignf(sqrtf(fmaxf(0.0f, 0.5f * (1.0f - c))), sn);
    float sh_b = __fdividef(0.5f * sn, ch);
    sh = (ch > 0.1f) ? sh_b : sh_a;
}
static __device__ __forceinline__ float epilogue(
    float x0, float x1, float r, float cb, float sb,
    const float* wv, const float* pv, float lm)
{
    float s2  = fmaf(x0, x0, x1 * x1);
    float ri0 = rsqrtf(s2);
    float r0  = s2 * ri0;
    float c   = x0 * ri0, sn = x1 * ri0;
    float sh, ch; halfang(c, sn, sh, ch);
    float sq  = sqrtf(r0);
    float v0  = sq * sh;
    float v1  = r0 * sn;
    float v2  = (r0 * sq) * fmaf(sn, ch, c * sh);
    float shb, chb; halfang(cb, sb, shb, chb);
    float u0 = shb, u1 = sb, u2 = fmaf(sb, chb, cb * shb);
    float t  = fminf(fmaxf(fmaf(2.5f, r, -1.25f), 0.0f), 1.0f);
    float t3 = t * t * t;
    float yita = fmaf(fmaf(fmaf(-6.0f, t, 15.0f), t, -10.0f), t3, 1.0f);
    float rp = wv[0] + yita * wv[4]
             + fmaf(wv[5], yita, wv[1]) * v0
             + fmaf(wv[6], yita, wv[2]) * v1
             + fmaf(wv[7], yita, wv[3]) * v2;
    float s  = fmaf(pv[1], u0, fmaf(pv[2], u1, fmaf(pv[3], u2, pv[0])));
    float sp = s * yita * __powf(r, lm);
    return rp + sp;
}

// ---------------- stage kernel: 8 blocks, one segment each ----------------
__global__ void stage_kernel(const float* __restrict__ Ww1, const float* __restrict__ bw1,
                             const float* __restrict__ Ww2, const float* __restrict__ bw2,
                             const float* __restrict__ Ww3, const float* __restrict__ bw3,
                             const float* __restrict__ Ww4, const float* __restrict__ bw4,
                             const float* __restrict__ Wp1, const float* __restrict__ bp1,
                             const float* __restrict__ Wp2, const float* __restrict__ bp2,
                             const float* __restrict__ Wp3, const float* __restrict__ bp3,
                             const float* __restrict__ Wp4, const float* __restrict__ bp4)
{
    struct WSeg { const float* w; const float* b; int off, NT, KT, KI, NO, fold; };
    const WSeg ws[8] = {
        {Ww1, bw1, PW1, 4, 1, 2, 30, 1},  {Ww2, bw2, PW2, 4, 2, 30, 30, 1},
        {Ww3, bw3, PW3, 4, 2, 30, 30, 1}, {Ww4, bw4, PW4, 1, 2, 30, 8, 1},
        {Wp1, bp1, PP1, 2, 1, 2, 15, 1},  {Wp2, bp2, PP2, 2, 1, 15, 15, 0},
        {Wp3, bp3, PP3, 2, 1, 15, 15, 0}, {Wp4, bp4, PP4, 1, 1, 15, 4, 0},
    };
    const WSeg s = ws[blockIdx.x];
    int n_u32 = s.NT * s.KT * 64;
    for (int t = threadIdx.x; t < n_u32; t += 128) {
        int pairIdx = t >> 1, half = t & 1;
        int lanep = pairIdx & 31, blk = pairIdx >> 5;
        int nt = blk / s.KT, kt = blk - nt * s.KT;
        int gg = lanep >> 2, qq = lanep & 3;
        int n = nt * 8 + gg;
        int k0 = kt * 16 + 2 * qq + (half ? 8 : 0);
        float v0f = 0.f, v1f = 0.f;
        if (n < s.NO) {
            for (int e = 0; e < 2; e++) {
                int k = k0 + e;
                float v = 0.f;
                if (k < s.KI) v = s.w[k * s.NO + n];
                else if (s.fold && k == s.KI) {
                    v = __half2float(__float2half(s.b[n]));     // hi
                } else if (s.fold && k == s.KI + 1) {
                    float bv = s.b[n];
                    v = bv - __half2float(__float2half(bv));    // lo
                }
                if (e == 0) v0f = v; else v1f = v;
            }
        }
        ((u32*)g_PK)[s.off * 2 + t] = f22h2(v0f, v1f);
    }
}

// ---------------- main kernel: 64 points/warp; packed LDS.64 fragments ----------------
__global__ void __launch_bounds__(128)
mlp2d_kernel(const float* __restrict__ x,   const float* __restrict__ imv,
             const float* __restrict__ lmbd,
             const float* __restrict__ bp2, const float* __restrict__ bp3,
             const float* __restrict__ bp4,
             float* __restrict__ out, long long N)
{
    __shared__ alignas(16) uint2 PK[PK_TOTAL];
    __shared__ alignas(16) float XF[4][256];
    __shared__ alignas(16) float HB[4][64 * HSTRIDE];
    __shared__ float scons[3];

    const int tid = threadIdx.x;

    // ---- copy packed weights global -> smem (vectorized) ----
    {
        const uint4* src = (const uint4*)g_PK;
        uint4* dst = (uint4*)PK;
#pragma unroll
        for (int t = tid; t < PK_TOTAL / 2; t += 128)
            dst[t] = src[t];
        if (tid == 0) { scons[0] = imv[0]; scons[1] = imv[1]; scons[2] = lmbd[0]; }
    }
    __syncthreads();

    const int lane = tid & 31;
    const int warp = tid >> 5;
    const int g = lane >> 2;
    const int qi = lane & 3;

    long long warpBase = ((long long)blockIdx.x * 4 + warp) * 64;
    if (warpBase >= N) return;

    // ---- load my 2 points + geometry; stage inputs ----
    long long i0 = warpBase + 2 * lane;
    long long iload = (i0 + 1 < N) ? i0 : (N - 2);
    float4 p = *(const float4*)(x + 2 * (size_t)iload);
    float xa0 = p.x, xa1 = p.y, xb0 = p.z, xb1 = p.w;

    const float im0 = scons[0], im1 = scons[1], lm = scons[2];
    float dA0 = xa0 - im0, dA1 = xa1 - im1;
    float rsA = fmaf(dA0, dA0, dA1 * dA1);
    float riA = rsqrtf(rsA);
    float rA = rsA * riA, cbA = dA0 * riA, sbA = dA1 * riA;
    float dB0 = xb0 - im0, dB1 = xb1 - im1;
    float rsB = fmaf(dB0, dB0, dB1 * dB1);
    float riB = rsqrtf(rsB);
    float rB = rsB * riB, cbB = dB0 * riB, sbB = dB1 * riB;

    float* Xb = &XF[warp][0];
    float* Fb = &XF[warp][128];
    float* Hb = &HB[warp][0];
    {
        int r0 = 2 * lane, r1 = r0 + 1;
        Xb[2 * r0] = xa0; Xb[2 * r0 + 1] = xa1;
        Xb[2 * r1] = xb0; Xb[2 * r1 + 1] = xb1;
        Fb[2 * r0] = cbA; Fb[2 * r0 + 1] = sbA;
        Fb[2 * r1] = cbB; Fb[2 * r1 + 1] = sbB;
    }
    __syncwarp();

    // ---- per-lane segment pointers ----
    const uint2* pw1 = PK + PW1 + lane;
    const uint2* pw2 = PK + PW2 + lane;
    const uint2* pw3 = PK + PW3 + lane;
    const uint2* pw4 = PK + PW4 + lane;
    const uint2* pp1 = PK + PP1 + lane;
    const uint2* pp2 = PK + PP2 + lane;
    const uint2* pp3 = PK + PP3 + lane;
    const uint2* pp4 = PK + PP4 + lane;

    // ---- fp32 bias registers for p2/p3/p4 ----
    float2 bbp2[2], bbp3[2], bbp4[1];
    {
        int c0 = 2 * qi;
#pragma unroll
        for (int nt = 0; nt < 2; nt++) {
            int c = nt * 8 + c0;
            bbp2[nt].x = (c < 15) ? bp2[c] : 0.f;
            bbp2[nt].y = (c + 1 < 15) ? bp2[c + 1] : 0.f;
            bbp3[nt].x = (c < 15) ? bp3[c] : 0.f;
            bbp3[nt].y = (c + 1 < 15) ? bp3[c + 1] : 0.f;
        }
        bbp4[0].x = (c0 < 4) ? bp4[c0] : 0.f;
        bbp4[0].y = (c0 + 1 < 4) ? bp4[c0 + 1] : 0.f;
    }

    // ---- per-M-tile network ----
#pragma unroll 1
    for (int mt = 0; mt < 4; mt++) {
        int row0 = mt * 16 + g, row1 = row0 + 8;

        // ===== w-MLP =====
        u32 aL1[1][4];
        aL1[0][0] = (qi == 0) ? f22h2(Xb[2 * row0], Xb[2 * row0 + 1])
                              : ((qi == 1) ? H2_ONE_ONE : 0u);   // k=2 hi, k=3 lo
        aL1[0][1] = (qi == 0) ? f22h2(Xb[2 * row1], Xb[2 * row1 + 1])
                              : ((qi == 1) ? H2_ONE_ONE : 0u);
        aL1[0][2] = 0u; aL1[0][3] = 0u;

        float cw[4][4];
        zero4<4>(cw);
        mma_pk<4, 1>(cw, aL1, pw1);

        u32 aw[2][4];
        act_trans_w(aw, cw, qi);
        zero4<4>(cw);
        mma_pk<4, 2>(cw, aw, pw2);

        act_trans_w(aw, cw, qi);
        zero4<4>(cw);
        mma_pk<4, 2>(cw, aw, pw3);

        act_trans_w(aw, cw, qi);
        float c4[1][4];
        zero4<1>(c4);
        mma_pk<1, 2>(c4, aw, pw4);

        Hb[row0 * HSTRIDE + 2 * qi]     = c4[0][0];
        Hb[row0 * HSTRIDE + 2 * qi + 1] = c4[0][1];
        Hb[row1 * HSTRIDE + 2 * qi]     = c4[0][2];
        Hb[row1 * HSTRIDE + 2 * qi + 1] = c4[0][3];

        // ===== phi-MLP =====
        u32 aP1[1][4];
        aP1[0][0] = (qi == 0) ? f22h2(Fb[2 * row0], Fb[2 * row0 + 1])
                              : ((qi == 1) ? H2_ONE_ONE : 0u);
        aP1[0][1] = (qi == 0) ? f22h2(Fb[2 * row1], Fb[2 * row1 + 1])
                              : ((qi == 1) ? H2_ONE_ONE : 0u);
        aP1[0][2] = 0u; aP1[0][3] = 0u;

        float cp[2][4];
        zero4<2>(cp);
        mma_pk<2, 1>(cp, aP1, pp1);

        u32 ap[1][4];
        act_trans_p(ap[0], cp, qi);
        binit<2>(cp, bbp2);
        mma_pk<2, 1>(cp, ap, pp2);

        act_trans_p(ap[0], cp, qi);
        binit<2>(cp, bbp3);
        mma_pk<2, 1>(cp, ap, pp3);

        act_trans_p(ap[0], cp, qi);
        float cp4[1][4];
        binit<1>(cp4, bbp4);
        mma_pk<1, 1>(cp4, ap, pp4);

        if (qi < 2) {
            Hb[row0 * HSTRIDE + 8 + 2 * qi]     = cp4[0][0];
            Hb[row0 * HSTRIDE + 8 + 2 * qi + 1] = cp4[0][1];
            Hb[row1 * HSTRIDE + 8 + 2 * qi]     = cp4[0][2];
            Hb[row1 * HSTRIDE + 8 + 2 * qi + 1] = cp4[0][3];
        }
    }
    __syncwarp();

    // ---- epilogue on my own 2 points ----
    {
        int r0 = 2 * lane, r1 = r0 + 1;
        float wv[8], pv[4];
#pragma unroll
        for (int j = 0; j < 8; j++) wv[j] = Hb[r0 * HSTRIDE + j];
#pragma unroll
        for (int j = 0; j < 4; j++) pv[j] = Hb[r0 * HSTRIDE + 8 + j];
        float eA = epilogue(xa0, xa1, rA, cbA, sbA, wv, pv, lm);

#pragma unroll
        for (int j = 0; j < 8; j++) wv[j] = Hb[r1 * HSTRIDE + j];
#pragma unroll
        for (int j = 0; j < 4; j++) pv[j] = Hb[r1 * HSTRIDE + 8 + j];
        float eB = epilogue(xb0, xb1, rB, cbB, sbB, wv, pv, lm);

        if (i0 + 1 < N) {
            *(float2*)(out + i0) = make_float2(eA, eB);
        } else if (i0 < N) {
            out[i0] = eA;
        }
    }
}

extern "C" void kernel_launch(void* const* d_in, const int* in_sizes, int n_in,
                              void* d_out, int out_size)
{
    const float* x    = (const float*)d_in[0];
    const float* imv  = (const float*)d_in[1];
    const float* lmbd = (const float*)d_in[2];
    const float* Ww1  = (const float*)d_in[3];
    const float* bw1  = (const float*)d_in[4];
    const float* Ww2  = (const float*)d_in[5];
    const float* bw2  = (const float*)d_in[6];
    const float* Ww3  = (const float*)d_in[7];
    const float* bw3  = (const float*)d_in[8];
    const float* Ww4  = (const float*)d_in[9];
    const float* bw4  = (const float*)d_in[10];
    const float* Wp1  = (const float*)d_in[11];
    const float* bp1  = (const float*)d_in[12];
    const float* Wp2  = (const float*)d_in[13];
    const float* bp2  = (const float*)d_in[14];
    const float* Wp3  = (const float*)d_in[15];
    const float* bp3  = (const float*)d_in[16];
    const float* Wp4  = (const float*)d_in[17];
    const float* bp4  = (const float*)d_in[18];

    long long N = out_size;
    long long blocks = (N + 255) / 256;

    stage_kernel<<<8, 128>>>(Ww1, bw1, Ww2, bw2, Ww3, bw3, Ww4, bw4,
                             Wp1, bp1, Wp2, bp2, Wp3, bp3, Wp4, bp4);
    mlp2d_kernel<<<(int)blocks, 128>>>(x, imv, lmbd, bp2, bp3, bp4,
                                       (float*)d_out, N);
}